// round 16
// baseline (speedup 1.0000x reference)
#include <cuda_runtime.h>
#include <cuda_fp16.h>
#include <math.h>
#include <stdint.h>

// Problem constants
#define Hd 2048
#define Id 4096
#define NE 8
#define T  4096

// GEMM tiling: CTA = 64m x 256n, BK=32 (fp16), 256 threads / 8 warps, 2 CTA/SM
#define BM 64
#define BK 32
#define THREADS 256
#define ASTR 40                       // halves per A row (32 + 8 pad) -> 80 B
#define ABYTES (BM * ASTR * 2)        // 5120
#define BSTR 264                      // halves per B k-row (256 + 8 pad) -> 528 B
#define BBYTES (BK * BSTR * 2)        // 16896
#define STAGE_BYTES (ABYTES + BBYTES) // 22016
#define NSTAGES 5
#define DYN_SMEM (NSTAGES * STAGE_BYTES)   // 110080 -> still 2 CTAs/SM

#define NCHUNK 4                      // gate/up convert column chunks
#define CHUNK_COLS (Id / NCHUNK)      // 1024 columns per chunk

// ---------------------------------------------------------------------------
// Static device scratch
// ---------------------------------------------------------------------------
#define GU_ROWS 9216
__device__ int    g_count[NE];
__device__ int    g_segbase[NE];
__device__ int    g_tok[NE][T];
__device__ int    g_sE[T * 2];
__device__ int    g_sP[T * 2];
__device__ float  g_sW[T * 2];
__device__ __align__(256) __half g_xh[(size_t)T * Hd];
__device__ __align__(256) __half g_gph[(size_t)NE * Hd * Id];
__device__ __align__(256) __half g_uph[(size_t)NE * Hd * Id];
__device__ __align__(256) __half g_dwh[(size_t)NE * Id * Hd];
__device__ __align__(256) __half g_guh[(size_t)GU_ROWS * Id];
__device__ __align__(256) float  g_scr[(size_t)GU_ROWS * Hd];

// ---------------------------------------------------------------------------
// PTX helpers (compute_103-legal)
// ---------------------------------------------------------------------------
__device__ __forceinline__ void cp16(uint32_t dst, const void* src) {
    asm volatile("cp.async.cg.shared.global [%0], [%1], 16;" :: "r"(dst), "l"(src));
}
__device__ __forceinline__ void ldm4(uint32_t* r, uint32_t addr) {
    asm volatile("ldmatrix.sync.aligned.m8n8.x4.shared.b16 {%0,%1,%2,%3}, [%4];"
                 : "=r"(r[0]), "=r"(r[1]), "=r"(r[2]), "=r"(r[3]) : "r"(addr));
}
__device__ __forceinline__ void ldm4t(uint32_t* r, uint32_t addr) {
    asm volatile("ldmatrix.sync.aligned.m8n8.x4.trans.shared.b16 {%0,%1,%2,%3}, [%4];"
                 : "=r"(r[0]), "=r"(r[1]), "=r"(r[2]), "=r"(r[3]) : "r"(addr));
}
__device__ __forceinline__ void mma16(float* c, const uint32_t* a, uint32_t b0, uint32_t b1) {
    asm volatile("mma.sync.aligned.m16n8k16.row.col.f32.f16.f16.f32 "
        "{%0,%1,%2,%3}, {%4,%5,%6,%7}, {%8,%9}, {%0,%1,%2,%3};"
        : "+f"(c[0]), "+f"(c[1]), "+f"(c[2]), "+f"(c[3])
        : "r"(a[0]), "r"(a[1]), "r"(a[2]), "r"(a[3]), "r"(b0), "r"(b1));
}
__device__ __forceinline__ float gelu_tanh(float v) {
    const float c = 0.7978845608028654f;
    float inner = c * (v + 0.044715f * v * v * v);
    return 0.5f * v * (1.0f + tanhf(inner));
}
// Pipeline wait: guarantee stage s resident given groups 0..min(s+3, nst-1) issued.
#define PIPE_WAIT(s, nst)                                                   \
    do {                                                                    \
        int rem = (nst) - 1 - (s);                                          \
        if (rem >= 3)      asm volatile("cp.async.wait_group 3;" ::: "memory"); \
        else if (rem == 2) asm volatile("cp.async.wait_group 2;" ::: "memory"); \
        else if (rem == 1) asm volatile("cp.async.wait_group 1;" ::: "memory"); \
        else               asm volatile("cp.async.wait_group 0;" ::: "memory"); \
    } while (0)

// ---------------------------------------------------------------------------
// fp32 -> fp16 conversion (grid-stride, float4)
// ---------------------------------------------------------------------------
__global__ void cvt_kernel(const float* __restrict__ s, __half* __restrict__ d, int n4) {
    int i = blockIdx.x * blockDim.x + threadIdx.x;
    int stride = gridDim.x * blockDim.x;
    for (; i < n4; i += stride) {
        float4 v = ((const float4*)s)[i];
        __half2 h0 = __floats2half2_rn(v.x, v.y);
        __half2 h1 = __floats2half2_rn(v.z, v.w);
        ((__half2*)d)[2 * i]     = h0;
        ((__half2*)d)[2 * i + 1] = h1;
    }
}

// Column-chunked convert for a [NE*Hd, Id] fp32 tensor: cols [c0, c0+CHUNK_COLS).
__global__ void cvt_cols_kernel(const float* __restrict__ s, __half* __restrict__ d, int c0) {
    int i = blockIdx.x * blockDim.x + threadIdx.x;   // over rows * (CHUNK_COLS/4)
    int stride = gridDim.x * blockDim.x;
    const int J = CHUNK_COLS / 4;                    // 256 float4 per row-chunk
    const int n = NE * Hd * J;
    for (; i < n; i += stride) {
        int row = i / J, j = i - row * J;
        size_t idx = (size_t)row * (Id / 4) + (c0 >> 2) + j;
        float4 v = ((const float4*)s)[idx];
        __half2 h0 = __floats2half2_rn(v.x, v.y);
        __half2 h1 = __floats2half2_rn(v.z, v.w);
        ((__half2*)d)[2 * idx]     = h0;
        ((__half2*)d)[2 * idx + 1] = h1;
    }
}

// ---------------------------------------------------------------------------
// Router + bookkeeping
// ---------------------------------------------------------------------------
__global__ void zero_counts_kernel() {
    if (threadIdx.x < NE) g_count[threadIdx.x] = 0;
}
__global__ void prefix_kernel() {
    if (threadIdx.x == 0) {
        int b = 0;
        for (int e = 0; e < NE; e++) {
            g_segbase[e] = b;
            b += ((g_count[e] + BM - 1) / BM) * BM;
        }
    }
}

__global__ void router_kernel(const float* __restrict__ x,
                              const float* __restrict__ gw,
                              float* __restrict__ out_logits) {
    int warp = (blockIdx.x * blockDim.x + threadIdx.x) >> 5;
    int lane = threadIdx.x & 31;
    if (warp >= T) return;
    const float* xr = x + (size_t)warp * Hd;
    float acc[NE];
#pragma unroll
    for (int e = 0; e < NE; e++) acc[e] = 0.0f;
    for (int h = lane; h < Hd; h += 32) {
        float xv = xr[h];
        const float* g = gw + (size_t)h * NE;
#pragma unroll
        for (int e = 0; e < NE; e++) acc[e] = fmaf(xv, g[e], acc[e]);
    }
#pragma unroll
    for (int e = 0; e < NE; e++) {
#pragma unroll
        for (int off = 16; off; off >>= 1)
            acc[e] += __shfl_xor_sync(0xffffffffu, acc[e], off);
    }
    if (lane == 0) {
        float* dst = out_logits + (size_t)warp * NE;
#pragma unroll
        for (int e = 0; e < NE; e++) dst[e] = acc[e];
        float l0 = -3.4e38f; int e0 = 0;
#pragma unroll
        for (int e = 0; e < NE; e++)
            if (acc[e] > l0) { l0 = acc[e]; e0 = e; }
        float l1 = -3.4e38f; int e1 = 0;
#pragma unroll
        for (int e = 0; e < NE; e++)
            if (e != e0 && acc[e] > l1) { l1 = acc[e]; e1 = e; }
        float w1 = __expf(l1 - l0);
        float inv = 1.0f / (1.0f + w1);
        int p0 = atomicAdd(&g_count[e0], 1);
        g_tok[e0][p0] = warp;
        g_sE[2 * warp] = e0; g_sP[2 * warp] = p0; g_sW[2 * warp] = inv;
        int p1 = atomicAdd(&g_count[e1], 1);
        g_tok[e1][p1] = warp;
        g_sE[2 * warp + 1] = e1; g_sP[2 * warp + 1] = p1; g_sW[2 * warp + 1] = w1 * inv;
    }
}

// ---------------------------------------------------------------------------
// Gate+Up GEMM (fp16 mma.sync): per CTA 64m x (128 gate + 128 up), K=Hd.
// n_base: n-tile offset (column-chunked launches).
// ---------------------------------------------------------------------------
__global__ __launch_bounds__(THREADS, 2)
void gateup_mma(int n_base) {
    int e  = blockIdx.z;
    int ne = g_count[e];
    int m0 = blockIdx.x * BM;
    if (m0 >= ne) return;
    int n0 = (n_base + blockIdx.y) * 128;

    extern __shared__ char smem[];
    uint32_t sbase = (uint32_t)__cvta_generic_to_shared(smem);
    __shared__ int rows[BM];

    int tid = threadIdx.x;
    int lane = tid & 31, wid = tid >> 5;
    int wm = wid & 1, wn = wid >> 1;

    if (tid < BM) {
        int m = m0 + tid;
        rows[tid] = g_tok[e][m < ne ? m : (ne - 1)];
    }
    __syncthreads();

    const __half* gbh = g_gph + (size_t)e * Hd * Id + n0;
    const __half* ubh = g_uph + (size_t)e * Hd * Id + n0;

    uint32_t a_lane = sbase + (uint32_t)((wm * 32 + (lane & 15)) * (ASTR * 2) + (lane >> 4) * 16);
    uint32_t b_lane = sbase + (uint32_t)ABYTES
                    + (uint32_t)((((lane & 7) + ((lane >> 3) & 1) * 8) * (BSTR * 2)) + (lane >> 4) * 16);
    int nmap2[4] = { wn * 32, wn * 32 + 16, 128 + wn * 32, 128 + wn * 32 + 16 };

    float c[2][8][4];
#pragma unroll
    for (int i = 0; i < 2; i++)
#pragma unroll
        for (int j = 0; j < 8; j++)
#pragma unroll
            for (int q = 0; q < 4; q++) c[i][j][q] = 0.0f;

    const int NST = Hd / BK;   // 64

    auto issue = [&](int s) {
        int k0 = s * BK;
        uint32_t a_s = sbase + (uint32_t)((s % NSTAGES) * STAGE_BYTES);
        uint32_t b_s = a_s + ABYTES;
        {
            int m = tid >> 2, ch = tid & 3;
            cp16(a_s + m * (ASTR * 2) + ch * 16,
                 g_xh + (size_t)rows[m] * Hd + k0 + ch * 8);
        }
#pragma unroll
        for (int i = 0; i < 4; i++) {
            int cidx = tid + i * 256;
            int k = cidx >> 5, nn = (cidx & 31) * 8;
            const __half* src = (nn < 128) ? (gbh + (size_t)(k0 + k) * Id + nn)
                                           : (ubh + (size_t)(k0 + k) * Id + (nn - 128));
            cp16(b_s + k * (BSTR * 2) + nn * 2, src);
        }
        asm volatile("cp.async.commit_group;" ::: "memory");
    };

    issue(0); issue(1); issue(2); issue(3);

    for (int s = 0; s < NST; s++) {
        PIPE_WAIT(s, NST);
        __syncthreads();
        if (s + 4 < NST) issue(s + 4);

        uint32_t stg = (uint32_t)((s % NSTAGES) * STAGE_BYTES);
#pragma unroll
        for (int kk = 0; kk < 2; kk++) {
            uint32_t af[2][4], bf[4][4];
#pragma unroll
            for (int i = 0; i < 2; i++)
                ldm4(af[i], a_lane + stg + (uint32_t)(i * 16 * ASTR * 2 + kk * 32));
#pragma unroll
            for (int j2 = 0; j2 < 4; j2++)
                ldm4t(bf[j2], b_lane + stg + (uint32_t)(kk * 16 * BSTR * 2 + nmap2[j2] * 2));
#pragma unroll
            for (int j = 0; j < 8; j++) {
                uint32_t b0 = bf[j >> 1][(j & 1) * 2];
                uint32_t b1 = bf[j >> 1][(j & 1) * 2 + 1];
#pragma unroll
                for (int i = 0; i < 2; i++) mma16(c[i][j], af[i], b0, b1);
            }
        }
    }

    // epilogue: gu = gelu(gate) * up -> fp16 scratch
    int seg = g_segbase[e] + m0;
#pragma unroll
    for (int i = 0; i < 2; i++) {
        int r0 = wm * 32 + i * 16 + (lane >> 2);
#pragma unroll
        for (int j = 0; j < 4; j++) {
            int nc = n0 + wn * 32 + j * 8 + (lane & 3) * 2;
            float* gg = c[i][j]; float* uu = c[i][j + 4];
            __half2 v0 = __floats2half2_rn(gelu_tanh(gg[0]) * uu[0], gelu_tanh(gg[1]) * uu[1]);
            __half2 v1 = __floats2half2_rn(gelu_tanh(gg[2]) * uu[2], gelu_tanh(gg[3]) * uu[3]);
            *(__half2*)(g_guh + (size_t)(seg + r0) * Id + nc)     = v0;
            *(__half2*)(g_guh + (size_t)(seg + r0 + 8) * Id + nc) = v1;
        }
    }
}

// ---------------------------------------------------------------------------
// Down GEMM (fp16 mma.sync): per CTA 64m x 256n, K=Id.
// Writes raw per-slot results to g_scr (no atomics; weights applied in combine).
// ---------------------------------------------------------------------------
__global__ __launch_bounds__(THREADS, 2)
void down_mma(void) {
    int e  = blockIdx.z;
    int ne = g_count[e];
    int m0 = blockIdx.x * BM;
    if (m0 >= ne) return;
    int n0 = blockIdx.y * 256;

    extern __shared__ char smem[];
    uint32_t sbase = (uint32_t)__cvta_generic_to_shared(smem);

    int tid = threadIdx.x;
    int lane = tid & 31, wid = tid >> 5;
    int wm = wid & 1, wn = wid >> 1;

    int seg = g_segbase[e] + m0;
    const __half* abase = g_guh + (size_t)seg * Id;
    const __half* bbase = g_dwh + (size_t)e * Id * Hd + n0;

    uint32_t a_lane = sbase + (uint32_t)((wm * 32 + (lane & 15)) * (ASTR * 2) + (lane >> 4) * 16);
    uint32_t b_lane = sbase + (uint32_t)ABYTES
                    + (uint32_t)((((lane & 7) + ((lane >> 3) & 1) * 8) * (BSTR * 2)) + (lane >> 4) * 16);
    int nmap2[4] = { wn * 64, wn * 64 + 16, wn * 64 + 32, wn * 64 + 48 };

    float c[2][8][4];
#pragma unroll
    for (int i = 0; i < 2; i++)
#pragma unroll
        for (int j = 0; j < 8; j++)
#pragma unroll
            for (int q = 0; q < 4; q++) c[i][j][q] = 0.0f;

    const int NST = Id / BK;   // 128

    auto issue = [&](int s) {
        int k0 = s * BK;
        uint32_t a_s = sbase + (uint32_t)((s % NSTAGES) * STAGE_BYTES);
        uint32_t b_s = a_s + ABYTES;
        {
            int m = tid >> 2, ch = tid & 3;
            cp16(a_s + m * (ASTR * 2) + ch * 16,
                 abase + (size_t)m * Id + k0 + ch * 8);
        }
#pragma unroll
        for (int i = 0; i < 4; i++) {
            int cidx = tid + i * 256;
            int k = cidx >> 5, nn = (cidx & 31) * 8;
            cp16(b_s + k * (BSTR * 2) + nn * 2,
                 bbase + (size_t)(k0 + k) * Hd + nn);
        }
        asm volatile("cp.async.commit_group;" ::: "memory");
    };

    issue(0); issue(1); issue(2); issue(3);

    for (int s = 0; s < NST; s++) {
        PIPE_WAIT(s, NST);
        __syncthreads();
        if (s + 4 < NST) issue(s + 4);

        uint32_t stg = (uint32_t)((s % NSTAGES) * STAGE_BYTES);
#pragma unroll
        for (int kk = 0; kk < 2; kk++) {
            uint32_t af[2][4], bf[4][4];
#pragma unroll
            for (int i = 0; i < 2; i++)
                ldm4(af[i], a_lane + stg + (uint32_t)(i * 16 * ASTR * 2 + kk * 32));
#pragma unroll
            for (int j2 = 0; j2 < 4; j2++)
                ldm4t(bf[j2], b_lane + stg + (uint32_t)(kk * 16 * BSTR * 2 + nmap2[j2] * 2));
#pragma unroll
            for (int j = 0; j < 8; j++) {
                uint32_t b0 = bf[j >> 1][(j & 1) * 2];
                uint32_t b1 = bf[j >> 1][(j & 1) * 2 + 1];
#pragma unroll
                for (int i = 0; i < 2; i++) mma16(c[i][j], af[i], b0, b1);
            }
        }
    }

    // raw store epilogue (pad rows written harmlessly; combine never reads them)
#pragma unroll
    for (int i = 0; i < 2; i++) {
        int r0 = seg + wm * 32 + i * 16 + (lane >> 2);
#pragma unroll
        for (int j = 0; j < 8; j++) {
            int nc = n0 + wn * 64 + j * 8 + (lane & 3) * 2;
            *(float2*)(g_scr + (size_t)r0 * Hd + nc)       = make_float2(c[i][j][0], c[i][j][1]);
            *(float2*)(g_scr + (size_t)(r0 + 8) * Hd + nc) = make_float2(c[i][j][2], c[i][j][3]);
        }
    }
}

// ---------------------------------------------------------------------------
// Combine: out[t] = w0 * scr[slot0(t)] + w1 * scr[slot1(t)]
// ---------------------------------------------------------------------------
__global__ void combine_kernel(float* __restrict__ out) {
    int i = blockIdx.x * blockDim.x + threadIdx.x;   // T * Hd/4 threads
    int t  = i >> 9;            // Hd/4 = 512
    int c4 = i & 511;
    int r0 = g_segbase[g_sE[2 * t]]     + g_sP[2 * t];
    int r1 = g_segbase[g_sE[2 * t + 1]] + g_sP[2 * t + 1];
    float w0 = g_sW[2 * t], w1 = g_sW[2 * t + 1];
    float4 a = ((const float4*)g_scr)[(size_t)r0 * 512 + c4];
    float4 b = ((const float4*)g_scr)[(size_t)r1 * 512 + c4];
    float4 o;
    o.x = w0 * a.x + w1 * b.x;
    o.y = w0 * a.y + w1 * b.y;
    o.z = w0 * a.z + w1 * b.z;
    o.w = w0 * a.w + w1 * b.w;
    ((float4*)out)[i] = o;
}

// ---------------------------------------------------------------------------
extern "C" void kernel_launch(void* const* d_in, const int* in_sizes, int n_in,
                              void* d_out, int out_size) {
    const float* x         = (const float*)d_in[0];
    const float* gate_w    = (const float*)d_in[1];
    const float* gate_proj = (const float*)d_in[2];
    const float* up_proj   = (const float*)d_in[3];
    const float* down_proj = (const float*)d_in[4];
    float* out = (float*)d_out;

    float* out_final  = out;
    float* out_logits = out + (size_t)T * Hd;

    cudaFuncSetAttribute(gateup_mma, cudaFuncAttributeMaxDynamicSharedMemorySize, DYN_SMEM);
    cudaFuncSetAttribute(down_mma,   cudaFuncAttributeMaxDynamicSharedMemorySize, DYN_SMEM);

    // One-time resources: 1 stream + 6 events (Round-11 footprint class;
    // the Round-12 violation came from 8 extra streams).
    static __half *xh = nullptr, *gph = nullptr, *uph = nullptr, *dwh = nullptr;
    static cudaStream_t s1;
    static cudaEvent_t evFork, evDN, evC[NCHUNK];
    if (!xh) {
        cudaGetSymbolAddress((void**)&xh,  g_xh);
        cudaGetSymbolAddress((void**)&gph, g_gph);
        cudaGetSymbolAddress((void**)&uph, g_uph);
        cudaGetSymbolAddress((void**)&dwh, g_dwh);
        cudaStreamCreateWithFlags(&s1, cudaStreamNonBlocking);
        cudaEventCreateWithFlags(&evFork, cudaEventDisableTiming);
        cudaEventCreateWithFlags(&evDN,   cudaEventDisableTiming);
        for (int c = 0; c < NCHUNK; c++)
            cudaEventCreateWithFlags(&evC[c], cudaEventDisableTiming);
    }

    const int WN4 = (NE * Hd * Id) / 4;

    // Side stream: x convert, then gate/up in column chunks, then down_proj.
    cudaEventRecord(evFork, 0);
    cudaStreamWaitEvent(s1, evFork, 0);
    cvt_kernel<<<2048, 256, 0, s1>>>(x, xh, (T * Hd) / 4);
    for (int c = 0; c < NCHUNK; c++) {
        cvt_cols_kernel<<<4096, 256, 0, s1>>>(gate_proj, gph, c * CHUNK_COLS);
        cvt_cols_kernel<<<4096, 256, 0, s1>>>(up_proj,   uph, c * CHUNK_COLS);
        cudaEventRecord(evC[c], s1);
    }
    cvt_kernel<<<8192, 256, 0, s1>>>(down_proj, dwh, WN4);
    cudaEventRecord(evDN, s1);

    // Main stream: routing while the first chunk converts.
    zero_counts_kernel<<<1, 32>>>();
    router_kernel<<<T / 8, 256>>>(x, gate_w, out_logits);
    prefix_kernel<<<1, 1>>>();

    // gateup in 4 column-chunked sub-launches, each gated on its convert chunk.
    const int NT_PER_CHUNK = CHUNK_COLS / 128;   // 8 n-tiles per chunk
    for (int c = 0; c < NCHUNK; c++) {
        cudaStreamWaitEvent(0, evC[c], 0);
        dim3 g1(T / BM, NT_PER_CHUNK, NE);
        gateup_mma<<<g1, THREADS, DYN_SMEM>>>(c * NT_PER_CHUNK);
    }

    cudaStreamWaitEvent(0, evDN, 0);
    dim3 g2(T / BM, Hd / 256, NE);
    down_mma<<<g2, THREADS, DYN_SMEM>>>();

    combine_kernel<<<(T * Hd / 4) / 256, 256>>>(out_final);
}